// round 1
// baseline (speedup 1.0000x reference)
#include <cuda_runtime.h>

#define N_NODES 100000
#define N_EDGES 1250000
#define D 64
#define SCAN_BLK 1024
#define N_SCAN_BLKS ((N_NODES + SCAN_BLK - 1) / SCAN_BLK)   // 98

// ---- scratch (no allocations allowed) ----
__device__ int   g_deg_out[N_NODES];
__device__ int   g_deg_in[N_NODES];
__device__ int   g_row_ptr[N_NODES];       // exclusive prefix sum of deg_in
__device__ int   g_cursor[N_NODES];
__device__ int   g_esrc[N_EDGES];          // edge sources, bucket-sorted by dst
__device__ int   g_blocksums[128];
__device__ float g_fs[N_NODES * D];        // features * deg_out^-1/2
__device__ float g_agg[N_NODES * D];       // aggregated (pre-GEMM)

// ---------------- zero degree arrays ----------------
__global__ void k_zero() {
    int i = blockIdx.x * blockDim.x + threadIdx.x;
    if (i < N_NODES) { g_deg_out[i] = 0; g_deg_in[i] = 0; }
}

// ---------------- degree histogram ----------------
__global__ void k_degrees(const int* __restrict__ src, const int* __restrict__ dst) {
    int i = blockIdx.x * blockDim.x + threadIdx.x;
    if (i < N_EDGES) {
        atomicAdd(&g_deg_out[src[i]], 1);
        atomicAdd(&g_deg_in [dst[i]], 1);
    }
}

// ---------------- pre-scale features by deg_out^-1/2 ----------------
__global__ void k_prescale(const float* __restrict__ feat) {
    int idx = blockIdx.x * blockDim.x + threadIdx.x;   // one float4 per thread
    if (idx < N_NODES * (D / 4)) {
        int node = idx / (D / 4);
        float s = rsqrtf((float)max(g_deg_out[node], 1));
        float4 v = ((const float4*)feat)[idx];
        v.x *= s; v.y *= s; v.z *= s; v.w *= s;
        ((float4*)g_fs)[idx] = v;
    }
}

// ---------------- 3-phase exclusive scan of deg_in ----------------
__global__ void k_scan1() {
    __shared__ int sh[SCAN_BLK];
    int i = blockIdx.x * SCAN_BLK + threadIdx.x;
    int v = (i < N_NODES) ? g_deg_in[i] : 0;
    sh[threadIdx.x] = v;
    __syncthreads();
    #pragma unroll
    for (int off = 1; off < SCAN_BLK; off <<= 1) {
        int t = 0;
        if (threadIdx.x >= off) t = sh[threadIdx.x - off];
        __syncthreads();
        if (threadIdx.x >= off) sh[threadIdx.x] += t;
        __syncthreads();
    }
    int incl = sh[threadIdx.x];
    if (i < N_NODES) g_row_ptr[i] = incl - v;           // exclusive
    if (threadIdx.x == SCAN_BLK - 1) g_blocksums[blockIdx.x] = incl;
}

__global__ void k_scan2() {
    __shared__ int sh[128];
    int v = (threadIdx.x < N_SCAN_BLKS) ? g_blocksums[threadIdx.x] : 0;
    sh[threadIdx.x] = v;
    __syncthreads();
    #pragma unroll
    for (int off = 1; off < 128; off <<= 1) {
        int t = 0;
        if (threadIdx.x >= off) t = sh[threadIdx.x - off];
        __syncthreads();
        if (threadIdx.x >= off) sh[threadIdx.x] += t;
        __syncthreads();
    }
    if (threadIdx.x < N_SCAN_BLKS) g_blocksums[threadIdx.x] = sh[threadIdx.x] - v; // exclusive
}

__global__ void k_scan3() {
    int i = blockIdx.x * blockDim.x + threadIdx.x;
    if (i < N_NODES) {
        int rp = g_row_ptr[i] + g_blocksums[i >> 10];
        g_row_ptr[i] = rp;
        g_cursor[i]  = rp;
    }
}

// ---------------- bucket-sort edges by dst ----------------
__global__ void k_bucket(const int* __restrict__ src, const int* __restrict__ dst) {
    int i = blockIdx.x * blockDim.x + threadIdx.x;
    if (i < N_EDGES) {
        int pos = atomicAdd(&g_cursor[dst[i]], 1);
        g_esrc[pos] = src[i];
    }
}

// ---------------- gather: one warp per dst node, no atomics ----------------
__global__ void k_gather() {
    int warp = (blockIdx.x * blockDim.x + threadIdx.x) >> 5;
    int lane = threadIdx.x & 31;
    if (warp >= N_NODES) return;
    int beg = g_row_ptr[warp];
    int end = beg + g_deg_in[warp];
    float2 acc = make_float2(0.f, 0.f);
    for (int e = beg; e < end; e++) {
        int s = g_esrc[e];                               // broadcast within warp
        float2 v = ((const float2*)g_fs)[s * (D / 2) + lane];
        acc.x += v.x; acc.y += v.y;
    }
    ((float2*)g_agg)[warp * (D / 2) + lane] = acc;
}

// ---------------- fused GEMM epilogue: out = (agg * deg_in^-1/2) @ W + bias ----
// 256 threads, 16 rows per block. Warp w handles rows 2w, 2w+1;
// lane: row = 2w + (lane>>4), 4 cols via float4 at 4*(lane&15).
__global__ void k_gemm(const float* __restrict__ weight,
                       const float* __restrict__ bias,
                       float* __restrict__ out) {
    __shared__ __align__(16) float Wsh[D * D];     // 16 KB
    __shared__ __align__(16) float fsh[16 * D];    // 4 KB
    int tid  = threadIdx.x;
    int base = blockIdx.x * 16;

    #pragma unroll
    for (int i = 0; i < 4; i++)
        ((float4*)Wsh)[tid + i * 256] = ((const float4*)weight)[tid + i * 256];

    {
        int node = base + (tid >> 4);
        int c4   = tid & 15;
        float s = rsqrtf((float)max(g_deg_in[node], 1));
        float4 v = ((const float4*)g_agg)[node * (D / 4) + c4];
        v.x *= s; v.y *= s; v.z *= s; v.w *= s;
        ((float4*)fsh)[(tid >> 4) * (D / 4) + c4] = v;
    }
    __syncthreads();

    int lane = tid & 31;
    int w    = tid >> 5;
    int rl   = 2 * w + (lane >> 4);
    int cg   = lane & 15;
    float4 acc = ((const float4*)bias)[cg];
    const float* fr = &fsh[rl * D];
    #pragma unroll
    for (int k = 0; k < D; k++) {
        float f = fr[k];
        float4 wv = *(const float4*)&Wsh[k * D + cg * 4];
        acc.x += f * wv.x; acc.y += f * wv.y;
        acc.z += f * wv.z; acc.w += f * wv.w;
    }
    ((float4*)out)[(base + rl) * (D / 4) + cg] = acc;
}

extern "C" void kernel_launch(void* const* d_in, const int* in_sizes, int n_in,
                              void* d_out, int out_size) {
    const float* features = (const float*)d_in[0];
    const float* weight   = (const float*)d_in[1];
    const float* bias     = (const float*)d_in[2];
    const int*   src      = (const int*)d_in[3];
    const int*   dst      = (const int*)d_in[4];
    float* out = (float*)d_out;

    k_zero    <<<(N_NODES + 255) / 256, 256>>>();
    k_degrees <<<(N_EDGES + 255) / 256, 256>>>(src, dst);
    k_prescale<<<(N_NODES * (D / 4) + 255) / 256, 256>>>(features);
    k_scan1   <<<N_SCAN_BLKS, SCAN_BLK>>>();
    k_scan2   <<<1, 128>>>();
    k_scan3   <<<(N_NODES + 255) / 256, 256>>>();
    k_bucket  <<<(N_EDGES + 255) / 256, 256>>>(src, dst);
    k_gather  <<<(N_NODES * 32 + 255) / 256, 256>>>();
    k_gemm    <<<N_NODES / 16, 256>>>(weight, bias, out);
}

// round 2
// speedup vs baseline: 1.1843x; 1.1843x over previous
#include <cuda_runtime.h>

#define N_NODES 100000
#define N_EDGES 1250000
#define D 64
#define SCAN_BLK 1024
#define N_SCAN_BLKS ((N_NODES + SCAN_BLK - 1) / SCAN_BLK)   // 98

typedef unsigned long long u64;

// ---- scratch (no allocations allowed) ----
__device__ int   g_deg_out[N_NODES];
__device__ int   g_deg_in[N_NODES];
__device__ int   g_row_ptr[N_NODES];
__device__ int   g_cursor[N_NODES];
__device__ int   g_esrc[N_EDGES];
__device__ int   g_blocksums[128];
__device__ float g_h[N_NODES * D];          // projected rows: (feat*deg_out^-1/2) @ W

// ---------------- f32x2 helpers ----------------
__device__ __forceinline__ u64 pack2(float f) {
    u64 r; asm("mov.b64 %0, {%1, %1};" : "=l"(r) : "f"(f)); return r;
}
__device__ __forceinline__ u64 ffma2(u64 a, u64 b, u64 c) {
    u64 d; asm("fma.rn.f32x2 %0, %1, %2, %3;" : "=l"(d) : "l"(a), "l"(b), "l"(c)); return d;
}
__device__ __forceinline__ float2 unpack2(u64 v) {
    float2 r; asm("mov.b64 {%0, %1}, %2;" : "=f"(r.x), "=f"(r.y) : "l"(v)); return r;
}

// ---------------- zero degree arrays ----------------
__global__ void k_zero() {
    int i = blockIdx.x * blockDim.x + threadIdx.x;
    if (i < N_NODES) { g_deg_out[i] = 0; g_deg_in[i] = 0; }
}

// ---------------- degree histogram (int4) ----------------
__global__ void k_degrees(const int* __restrict__ src, const int* __restrict__ dst) {
    int i = blockIdx.x * blockDim.x + threadIdx.x;
    if (i < N_EDGES / 4) {
        int4 s = ((const int4*)src)[i];
        int4 d = ((const int4*)dst)[i];
        atomicAdd(&g_deg_out[s.x], 1); atomicAdd(&g_deg_out[s.y], 1);
        atomicAdd(&g_deg_out[s.z], 1); atomicAdd(&g_deg_out[s.w], 1);
        atomicAdd(&g_deg_in[d.x], 1);  atomicAdd(&g_deg_in[d.y], 1);
        atomicAdd(&g_deg_in[d.z], 1);  atomicAdd(&g_deg_in[d.w], 1);
    }
}

// ---------------- projection: h = (feat * deg_out^-1/2) @ W ----------------
// 256 threads/block, block covers 256 rows. Thread: 4 rows x 16 cols.
// smem: W (4096 f) + feature tile 256 x 65 (padded, conflict-free).
#define PROJ_ROWS 256
#define FPAD 65
__global__ void __launch_bounds__(256, 2)
k_proj(const float* __restrict__ feat, const float* __restrict__ weight) {
    extern __shared__ float smem[];
    float* Wsh = smem;                 // 4096 floats
    float* fsh = smem + 4096;          // 256*65 floats

    int tid = threadIdx.x;
    int B0  = blockIdx.x * PROJ_ROWS;

    // load W (row-major; pairs 8B-aligned)
    #pragma unroll
    for (int i = 0; i < 4; i++)
        ((float4*)Wsh)[tid + i * 256] = ((const float4*)weight)[tid + i * 256];

    // load + prescale feature tile (scalar stores into padded layout)
    #pragma unroll
    for (int it = 0; it < 16; it++) {
        int idx = tid + it * 256;          // float4 index within tile
        int row = idx >> 4;
        int c4  = idx & 15;
        int gr  = B0 + row;
        float4 v = make_float4(0.f, 0.f, 0.f, 0.f);
        if (gr < N_NODES) {
            float s = rsqrtf((float)max(g_deg_out[gr], 1));
            v = ((const float4*)feat)[gr * 16 + c4];
            v.x *= s; v.y *= s; v.z *= s; v.w *= s;
        }
        float* p = &fsh[row * FPAD + c4 * 4];
        p[0] = v.x; p[1] = v.y; p[2] = v.z; p[3] = v.w;
    }
    __syncthreads();

    int cg = tid & 3;            // col group: 16 cols = 8 pairs
    int rg = tid >> 2;           // row group: 4 rows
    const u64* W2 = (const u64*)Wsh;
    const float* fr = &fsh[(rg * 4) * FPAD];

    u64 acc[4][8];
    #pragma unroll
    for (int r = 0; r < 4; r++)
        #pragma unroll
        for (int j = 0; j < 8; j++) acc[r][j] = 0ull;

    #pragma unroll 4
    for (int k = 0; k < D; k++) {
        u64 w[8];
        #pragma unroll
        for (int j = 0; j < 8; j++) w[j] = W2[k * 32 + cg * 8 + j];
        #pragma unroll
        for (int r = 0; r < 4; r++) {
            u64 ff = pack2(fr[r * FPAD + k]);
            #pragma unroll
            for (int j = 0; j < 8; j++) acc[r][j] = ffma2(ff, w[j], acc[r][j]);
        }
    }

    // store: 4 rows x 16 cols -> 4 float4 per row
    #pragma unroll
    for (int r = 0; r < 4; r++) {
        int gr = B0 + rg * 4 + r;
        if (gr < N_NODES) {
            #pragma unroll
            for (int q = 0; q < 4; q++) {
                float2 p0 = unpack2(acc[r][2 * q]);
                float2 p1 = unpack2(acc[r][2 * q + 1]);
                ((float4*)g_h)[gr * 16 + cg * 4 + q] = make_float4(p0.x, p0.y, p1.x, p1.y);
            }
        }
    }
}

// ---------------- warp-shuffle exclusive scan ----------------
__device__ __forceinline__ int warp_incl_scan(int v, int lane) {
    #pragma unroll
    for (int off = 1; off < 32; off <<= 1) {
        int t = __shfl_up_sync(0xFFFFFFFFu, v, off);
        if (lane >= off) v += t;
    }
    return v;
}

__global__ void k_scan1() {
    __shared__ int wsum[32];
    int i = blockIdx.x * SCAN_BLK + threadIdx.x;
    int lane = threadIdx.x & 31, w = threadIdx.x >> 5;
    int v = (i < N_NODES) ? g_deg_in[i] : 0;
    int incl = warp_incl_scan(v, lane);
    if (lane == 31) wsum[w] = incl;
    __syncthreads();
    if (w == 0) wsum[lane] = warp_incl_scan(wsum[lane], lane);
    __syncthreads();
    if (w > 0) incl += wsum[w - 1];
    if (i < N_NODES) g_row_ptr[i] = incl - v;
    if (threadIdx.x == SCAN_BLK - 1) g_blocksums[blockIdx.x] = incl;
}

__global__ void k_scan2() {
    __shared__ int wsum[4];
    int tid = threadIdx.x, lane = tid & 31, w = tid >> 5;
    int v = (tid < N_SCAN_BLKS) ? g_blocksums[tid] : 0;
    int incl = warp_incl_scan(v, lane);
    if (lane == 31) wsum[w] = incl;
    __syncthreads();
    if (tid == 0) {
        int s = 0;
        #pragma unroll
        for (int j = 0; j < 4; j++) { int t = wsum[j]; wsum[j] = s; s += t; }
    }
    __syncthreads();
    if (tid < N_SCAN_BLKS) g_blocksums[tid] = incl - v + wsum[w];
}

__global__ void k_scan3() {
    int i = blockIdx.x * blockDim.x + threadIdx.x;
    if (i < N_NODES) {
        int rp = g_row_ptr[i] + g_blocksums[i >> 10];
        g_row_ptr[i] = rp;
        g_cursor[i]  = rp;
    }
}

// ---------------- bucket-sort edges by dst (int4) ----------------
__global__ void k_bucket(const int* __restrict__ src, const int* __restrict__ dst) {
    int i = blockIdx.x * blockDim.x + threadIdx.x;
    if (i < N_EDGES / 4) {
        int4 s = ((const int4*)src)[i];
        int4 d = ((const int4*)dst)[i];
        g_esrc[atomicAdd(&g_cursor[d.x], 1)] = s.x;
        g_esrc[atomicAdd(&g_cursor[d.y], 1)] = s.y;
        g_esrc[atomicAdd(&g_cursor[d.z], 1)] = s.z;
        g_esrc[atomicAdd(&g_cursor[d.w], 1)] = s.w;
    }
}

// ---------------- gather + epilogue: out = segsum(h[src]) * deg_in^-1/2 + bias ----
__global__ void k_gather(const float* __restrict__ bias, float* __restrict__ out) {
    int node = (blockIdx.x * blockDim.x + threadIdx.x) >> 5;
    int lane = threadIdx.x & 31;
    if (node >= N_NODES) return;
    int beg = g_row_ptr[node];
    int deg = g_deg_in[node];
    int end = beg + deg;
    const float2* __restrict__ H2 = (const float2*)g_h;

    float2 a0 = {0.f, 0.f}, a1 = {0.f, 0.f}, a2 = {0.f, 0.f}, a3 = {0.f, 0.f};
    int e = beg;
    for (; e + 4 <= end; e += 4) {
        int s0 = __ldg(&g_esrc[e + 0]);
        int s1 = __ldg(&g_esrc[e + 1]);
        int s2 = __ldg(&g_esrc[e + 2]);
        int s3 = __ldg(&g_esrc[e + 3]);
        float2 v0 = H2[s0 * 32 + lane];
        float2 v1 = H2[s1 * 32 + lane];
        float2 v2 = H2[s2 * 32 + lane];
        float2 v3 = H2[s3 * 32 + lane];
        a0.x += v0.x; a0.y += v0.y;
        a1.x += v1.x; a1.y += v1.y;
        a2.x += v2.x; a2.y += v2.y;
        a3.x += v3.x; a3.y += v3.y;
    }
    for (; e < end; e++) {
        int s = __ldg(&g_esrc[e]);
        float2 v = H2[s * 32 + lane];
        a0.x += v.x; a0.y += v.y;
    }
    float sx = (a0.x + a1.x) + (a2.x + a3.x);
    float sy = (a0.y + a1.y) + (a2.y + a3.y);
    float sc = rsqrtf((float)max(deg, 1));
    float2 b = ((const float2*)bias)[lane];
    ((float2*)out)[node * 32 + lane] = make_float2(sx * sc + b.x, sy * sc + b.y);
}

extern "C" void kernel_launch(void* const* d_in, const int* in_sizes, int n_in,
                              void* d_out, int out_size) {
    const float* features = (const float*)d_in[0];
    const float* weight   = (const float*)d_in[1];
    const float* bias     = (const float*)d_in[2];
    const int*   src      = (const int*)d_in[3];
    const int*   dst      = (const int*)d_in[4];
    float* out = (float*)d_out;

    int proj_smem = (4096 + PROJ_ROWS * FPAD) * sizeof(float);   // ~82.6 KB
    cudaFuncSetAttribute(k_proj, cudaFuncAttributeMaxDynamicSharedMemorySize, proj_smem);

    k_zero    <<<(N_NODES + 255) / 256, 256>>>();
    k_degrees <<<(N_EDGES / 4 + 255) / 256, 256>>>(src, dst);
    k_proj    <<<(N_NODES + PROJ_ROWS - 1) / PROJ_ROWS, 256, proj_smem>>>(features, weight);
    k_scan1   <<<N_SCAN_BLKS, SCAN_BLK>>>();
    k_scan2   <<<1, 128>>>();
    k_scan3   <<<(N_NODES + 255) / 256, 256>>>();
    k_bucket  <<<(N_EDGES / 4 + 255) / 256, 256>>>(src, dst);
    k_gather  <<<(N_NODES * 32 + 255) / 256, 256>>>(bias, out);
}

// round 3
// speedup vs baseline: 1.2447x; 1.0510x over previous
#include <cuda_runtime.h>

#define N_NODES 100000
#define N_EDGES 1250000
#define D 64

#define SCAN_TPB 256
#define SCAN_ITEMS 16
#define SCAN_TILE (SCAN_TPB * SCAN_ITEMS)                       // 4096
#define N_TILES ((N_NODES + SCAN_TILE - 1) / SCAN_TILE)          // 25

typedef unsigned long long u64;

// ---- scratch (no allocations allowed) ----
__device__ int   g_deg_out[N_NODES];
__device__ int   g_deg_in[N_NODES];
__device__ int   g_row_ptr[N_NODES];
__device__ int   g_cursor[N_NODES];
__device__ int   g_esrc[N_EDGES];
__device__ u64   g_tile_state[N_TILES];     // flag (hi 32) | value (lo 32)
__device__ float g_h[N_NODES * D];          // projected rows

// ---------------- f32x2 helpers ----------------
__device__ __forceinline__ u64 pack2(float f) {
    u64 r; asm("mov.b64 %0, {%1, %1};" : "=l"(r) : "f"(f)); return r;
}
__device__ __forceinline__ u64 ffma2(u64 a, u64 b, u64 c) {
    u64 d; asm("fma.rn.f32x2 %0, %1, %2, %3;" : "=l"(d) : "l"(a), "l"(b), "l"(c)); return d;
}
__device__ __forceinline__ float2 unpack2(u64 v) {
    float2 r; asm("mov.b64 {%0, %1}, %2;" : "=f"(r.x), "=f"(r.y) : "l"(v)); return r;
}

// ---------------- degree histograms (split per branch) ----------------
__global__ void k_deg_out(const int* __restrict__ src) {
    int i = blockIdx.x * blockDim.x + threadIdx.x;
    if (i < N_EDGES / 4) {
        int4 s = ((const int4*)src)[i];
        atomicAdd(&g_deg_out[s.x], 1); atomicAdd(&g_deg_out[s.y], 1);
        atomicAdd(&g_deg_out[s.z], 1); atomicAdd(&g_deg_out[s.w], 1);
    }
}
__global__ void k_deg_in(const int* __restrict__ dst) {
    int i = blockIdx.x * blockDim.x + threadIdx.x;
    if (i < N_EDGES / 4) {
        int4 d = ((const int4*)dst)[i];
        atomicAdd(&g_deg_in[d.x], 1); atomicAdd(&g_deg_in[d.y], 1);
        atomicAdd(&g_deg_in[d.z], 1); atomicAdd(&g_deg_in[d.w], 1);
    }
}

// ---------------- projection: h = (feat * deg_out^-1/2) @ W ----------------
#define PROJ_ROWS 256
#define FPAD 65
__global__ void __launch_bounds__(256, 2)
k_proj(const float* __restrict__ feat, const float* __restrict__ weight) {
    extern __shared__ float smem[];
    float* Wsh = smem;                 // 4096 floats
    float* fsh = smem + 4096;          // 256*65 floats

    int tid = threadIdx.x;
    int B0  = blockIdx.x * PROJ_ROWS;

    #pragma unroll
    for (int i = 0; i < 4; i++)
        ((float4*)Wsh)[tid + i * 256] = ((const float4*)weight)[tid + i * 256];

    #pragma unroll
    for (int it = 0; it < 16; it++) {
        int idx = tid + it * 256;
        int row = idx >> 4;
        int c4  = idx & 15;
        int gr  = B0 + row;
        float4 v = make_float4(0.f, 0.f, 0.f, 0.f);
        if (gr < N_NODES) {
            float s = rsqrtf((float)max(g_deg_out[gr], 1));
            v = ((const float4*)feat)[gr * 16 + c4];
            v.x *= s; v.y *= s; v.z *= s; v.w *= s;
        }
        float* p = &fsh[row * FPAD + c4 * 4];
        p[0] = v.x; p[1] = v.y; p[2] = v.z; p[3] = v.w;
    }
    __syncthreads();

    int cg = tid & 3;
    int rg = tid >> 2;
    const u64* W2 = (const u64*)Wsh;
    const float* fr = &fsh[(rg * 4) * FPAD];

    u64 acc[4][8];
    #pragma unroll
    for (int r = 0; r < 4; r++)
        #pragma unroll
        for (int j = 0; j < 8; j++) acc[r][j] = 0ull;

    #pragma unroll 4
    for (int k = 0; k < D; k++) {
        u64 w[8];
        #pragma unroll
        for (int j = 0; j < 8; j++) w[j] = W2[k * 32 + cg * 8 + j];
        #pragma unroll
        for (int r = 0; r < 4; r++) {
            u64 ff = pack2(fr[r * FPAD + k]);
            #pragma unroll
            for (int j = 0; j < 8; j++) acc[r][j] = ffma2(ff, w[j], acc[r][j]);
        }
    }

    #pragma unroll
    for (int r = 0; r < 4; r++) {
        int gr = B0 + rg * 4 + r;
        if (gr < N_NODES) {
            #pragma unroll
            for (int q = 0; q < 4; q++) {
                float2 p0 = unpack2(acc[r][2 * q]);
                float2 p1 = unpack2(acc[r][2 * q + 1]);
                ((float4*)g_h)[gr * 16 + cg * 4 + q] = make_float4(p0.x, p0.y, p1.x, p1.y);
            }
        }
    }
}

// ---------------- single-pass decoupled-lookback scan of deg_in ----------------
__device__ __forceinline__ int warp_incl_scan(int v, int lane) {
    #pragma unroll
    for (int off = 1; off < 32; off <<= 1) {
        int t = __shfl_up_sync(0xFFFFFFFFu, v, off);
        if (lane >= off) v += t;
    }
    return v;
}

__global__ void __launch_bounds__(SCAN_TPB, 1) k_scan() {
    __shared__ int sh_warp[SCAN_TPB / 32];
    __shared__ int sh_prefix;
    int tile = blockIdx.x;
    int tid  = threadIdx.x, lane = tid & 31, w = tid >> 5;
    int base = tile * SCAN_TILE + tid * SCAN_ITEMS;

    int v[SCAN_ITEMS];
    #pragma unroll
    for (int q = 0; q < 4; q++) {
        int idx = base + q * 4;
        int4 t = make_int4(0, 0, 0, 0);
        if (idx + 3 < N_NODES) {
            t = *(const int4*)&g_deg_in[idx];
        } else {
            if (idx + 0 < N_NODES) t.x = g_deg_in[idx + 0];
            if (idx + 1 < N_NODES) t.y = g_deg_in[idx + 1];
            if (idx + 2 < N_NODES) t.z = g_deg_in[idx + 2];
            if (idx + 3 < N_NODES) t.w = g_deg_in[idx + 3];
        }
        v[q * 4 + 0] = t.x; v[q * 4 + 1] = t.y;
        v[q * 4 + 2] = t.z; v[q * 4 + 3] = t.w;
    }
    #pragma unroll
    for (int i = 1; i < SCAN_ITEMS; i++) v[i] += v[i - 1];
    int tsum = v[SCAN_ITEMS - 1];

    int incl = warp_incl_scan(tsum, lane);
    if (lane == 31) sh_warp[w] = incl;
    __syncthreads();
    if (w == 0 && lane < SCAN_TPB / 32) {
        int x = sh_warp[lane];
        #pragma unroll
        for (int off = 1; off < SCAN_TPB / 32; off <<= 1) {
            int t = __shfl_up_sync(0xFFu, x, off);
            if (lane >= off) x += t;
        }
        sh_warp[lane] = x;
    }
    __syncthreads();
    int thread_excl = incl - tsum + (w > 0 ? sh_warp[w - 1] : 0);
    int block_sum   = sh_warp[SCAN_TPB / 32 - 1];

    if (tid == 0) {
        u64 st = (tile == 0) ? ((2ull << 32) | (unsigned)block_sum)
                             : ((1ull << 32) | (unsigned)block_sum);
        atomicExch(&g_tile_state[tile], st);
        if (tile == 0) sh_prefix = 0;
    }
    if (tile > 0 && w == 0) {
        int idx = tile - 1 - lane;
        int pfx = 0;
        for (;;) {
            u64 st = (idx >= 0) ? atomicAdd(&g_tile_state[idx], 0ull) : (2ull << 32);
            unsigned f = (unsigned)(st >> 32);
            unsigned bal2 = __ballot_sync(0xFFFFFFFFu, f == 2);
            unsigned bal1 = __ballot_sync(0xFFFFFFFFu, f >= 1);
            int l2 = __ffs(bal2) - 1;                  // always >= 0 (OOB lanes give flag 2)
            unsigned below = (1u << l2) - 1u;
            if ((bal1 & below) == below) {
                int val = (lane <= l2) ? (int)(unsigned)(st & 0xFFFFFFFFu) : 0;
                #pragma unroll
                for (int o = 16; o; o >>= 1) val += __shfl_xor_sync(0xFFFFFFFFu, val, o);
                pfx = val;
                break;
            }
        }
        if (lane == 0) {
            sh_prefix = pfx;
            atomicExch(&g_tile_state[tile], (2ull << 32) | (unsigned)(pfx + block_sum));
        }
    }
    __syncthreads();
    int pfx = sh_prefix;

    #pragma unroll
    for (int i = 0; i < SCAN_ITEMS; i++) {
        int idx = base + i;
        if (idx < N_NODES) {
            int e = pfx + thread_excl + (i ? v[i - 1] : 0);
            g_row_ptr[idx] = e;
            g_cursor[idx]  = e;
        }
    }
}

// ---------------- bucket-sort edges by dst ----------------
__global__ void k_bucket(const int* __restrict__ src, const int* __restrict__ dst) {
    int i = blockIdx.x * blockDim.x + threadIdx.x;
    if (i < N_EDGES / 4) {
        int4 s = ((const int4*)src)[i];
        int4 d = ((const int4*)dst)[i];
        g_esrc[atomicAdd(&g_cursor[d.x], 1)] = s.x;
        g_esrc[atomicAdd(&g_cursor[d.y], 1)] = s.y;
        g_esrc[atomicAdd(&g_cursor[d.z], 1)] = s.z;
        g_esrc[atomicAdd(&g_cursor[d.w], 1)] = s.w;
    }
}

// ---------------- gather + epilogue ----------------
__global__ void k_gather(const float* __restrict__ bias, float* __restrict__ out) {
    int node = (blockIdx.x * blockDim.x + threadIdx.x) >> 5;
    int lane = threadIdx.x & 31;
    if (node >= N_NODES) return;
    int beg = g_row_ptr[node];
    int deg = g_deg_in[node];
    int end = beg + deg;
    const float2* __restrict__ H2 = (const float2*)g_h;

    float2 a0 = {0.f, 0.f}, a1 = {0.f, 0.f}, a2 = {0.f, 0.f}, a3 = {0.f, 0.f};
    int e = beg;
    for (; e + 4 <= end; e += 4) {
        int s0 = __ldg(&g_esrc[e + 0]);
        int s1 = __ldg(&g_esrc[e + 1]);
        int s2 = __ldg(&g_esrc[e + 2]);
        int s3 = __ldg(&g_esrc[e + 3]);
        float2 v0 = H2[s0 * 32 + lane];
        float2 v1 = H2[s1 * 32 + lane];
        float2 v2 = H2[s2 * 32 + lane];
        float2 v3 = H2[s3 * 32 + lane];
        a0.x += v0.x; a0.y += v0.y;
        a1.x += v1.x; a1.y += v1.y;
        a2.x += v2.x; a2.y += v2.y;
        a3.x += v3.x; a3.y += v3.y;
    }
    for (; e < end; e++) {
        int s = __ldg(&g_esrc[e]);
        float2 v = H2[s * 32 + lane];
        a0.x += v.x; a0.y += v.y;
    }
    float sx = (a0.x + a1.x) + (a2.x + a3.x);
    float sy = (a0.y + a1.y) + (a2.y + a3.y);
    float sc = rsqrtf((float)max(deg, 1));
    float2 b = ((const float2*)bias)[lane];
    ((float2*)out)[node * 32 + lane] = make_float2(sx * sc + b.x, sy * sc + b.y);
}

// ---------------- stream/event resources (host-side, created once) ----------------
struct GcnRes {
    cudaStream_t s2 = nullptr;
    cudaEvent_t  ev_fork = nullptr, ev_join = nullptr;
    GcnRes() {
        cudaStreamCreateWithFlags(&s2, cudaStreamNonBlocking);
        cudaEventCreateWithFlags(&ev_fork, cudaEventDisableTiming);
        cudaEventCreateWithFlags(&ev_join, cudaEventDisableTiming);
    }
};
static GcnRes g_res;

extern "C" void kernel_launch(void* const* d_in, const int* in_sizes, int n_in,
                              void* d_out, int out_size) {
    const float* features = (const float*)d_in[0];
    const float* weight   = (const float*)d_in[1];
    const float* bias     = (const float*)d_in[2];
    const int*   src      = (const int*)d_in[3];
    const int*   dst      = (const int*)d_in[4];
    float* out = (float*)d_out;

    if (!g_res.s2) {  // fallback if static init ran before CUDA was usable
        cudaStreamCreateWithFlags(&g_res.s2, cudaStreamNonBlocking);
        cudaEventCreateWithFlags(&g_res.ev_fork, cudaEventDisableTiming);
        cudaEventCreateWithFlags(&g_res.ev_join, cudaEventDisableTiming);
    }

    static void* p_deg_out = nullptr;
    static void* p_deg_in  = nullptr;
    static void* p_state   = nullptr;
    static bool  attr_set  = false;
    if (!p_deg_out) {
        cudaGetSymbolAddress(&p_deg_out, g_deg_out);
        cudaGetSymbolAddress(&p_deg_in,  g_deg_in);
        cudaGetSymbolAddress(&p_state,   g_tile_state);
    }
    int proj_smem = (4096 + PROJ_ROWS * FPAD) * sizeof(float);
    if (!attr_set) {
        cudaFuncSetAttribute(k_proj, cudaFuncAttributeMaxDynamicSharedMemorySize, proj_smem);
        attr_set = true;
    }

    cudaStream_t ms = 0;           // capture-origin (default) stream
    cudaStream_t s2 = g_res.s2;

    // fork: branch B on s2
    cudaEventRecord(g_res.ev_fork, ms);
    cudaStreamWaitEvent(s2, g_res.ev_fork, 0);

    // ---- branch B: deg_in -> scan -> bucket ----
    cudaMemsetAsync(p_deg_in, 0, N_NODES * sizeof(int), s2);
    cudaMemsetAsync(p_state,  0, N_TILES * sizeof(u64), s2);
    k_deg_in <<<(N_EDGES / 4 + 255) / 256, 256, 0, s2>>>(dst);
    k_scan   <<<N_TILES, SCAN_TPB, 0, s2>>>();
    k_bucket <<<(N_EDGES / 4 + 255) / 256, 256, 0, s2>>>(src, dst);
    cudaEventRecord(g_res.ev_join, s2);

    // ---- branch A: deg_out -> proj ----
    cudaMemsetAsync(p_deg_out, 0, N_NODES * sizeof(int), ms);
    k_deg_out<<<(N_EDGES / 4 + 255) / 256, 256, 0, ms>>>(src);
    k_proj   <<<(N_NODES + PROJ_ROWS - 1) / PROJ_ROWS, 256, proj_smem, ms>>>(features, weight);

    // join + gather
    cudaStreamWaitEvent(ms, g_res.ev_join, 0);
    k_gather <<<(N_NODES * 32 + 255) / 256, 256, 0, ms>>>(bias, out);
}

// round 4
// speedup vs baseline: 1.3032x; 1.0469x over previous
#include <cuda_runtime.h>
#include <cuda_fp16.h>

#define N_NODES 100000
#define N_EDGES 1250000
#define D 64

#define SCAN_TPB 256
#define SCAN_ITEMS 16
#define SCAN_TILE (SCAN_TPB * SCAN_ITEMS)                       // 4096
#define N_TILES ((N_NODES + SCAN_TILE - 1) / SCAN_TILE)          // 25

typedef unsigned long long u64;

// ---- scratch (no allocations allowed) ----
__device__ int    g_deg_out[N_NODES];
__device__ int    g_deg_in[N_NODES];
__device__ int    g_row_ptr[N_NODES];
__device__ int    g_cursor[N_NODES];
__device__ int    g_esrc[N_EDGES];
__device__ u64    g_tile_state[N_TILES];      // flag (hi 32) | value (lo 32)
__device__ __half g_h[N_NODES * D];           // projected rows (fp16)

// ---------------- f32x2 helpers ----------------
__device__ __forceinline__ u64 pack2(float f) {
    u64 r; asm("mov.b64 %0, {%1, %1};" : "=l"(r) : "f"(f)); return r;
}
__device__ __forceinline__ u64 ffma2(u64 a, u64 b, u64 c) {
    u64 d; asm("fma.rn.f32x2 %0, %1, %2, %3;" : "=l"(d) : "l"(a), "l"(b), "l"(c)); return d;
}
__device__ __forceinline__ float2 unpack2(u64 v) {
    float2 r; asm("mov.b64 {%0, %1}, %2;" : "=f"(r.x), "=f"(r.y) : "l"(v)); return r;
}
__device__ __forceinline__ unsigned cvt_h2(u64 v) {   // f32x2 pair -> packed half2
    float2 p = unpack2(v);
    unsigned r; asm("cvt.rn.f16x2.f32 %0, %2, %1;" : "=r"(r) : "f"(p.x), "f"(p.y));
    return r;
}

// ---------------- degree histograms (split per branch) ----------------
__global__ void k_deg_out(const int* __restrict__ src) {
    int i = blockIdx.x * blockDim.x + threadIdx.x;
    if (i < N_EDGES / 4) {
        int4 s = ((const int4*)src)[i];
        atomicAdd(&g_deg_out[s.x], 1); atomicAdd(&g_deg_out[s.y], 1);
        atomicAdd(&g_deg_out[s.z], 1); atomicAdd(&g_deg_out[s.w], 1);
    }
}
__global__ void k_deg_in(const int* __restrict__ dst) {
    int i = blockIdx.x * blockDim.x + threadIdx.x;
    if (i < N_EDGES / 4) {
        int4 d = ((const int4*)dst)[i];
        atomicAdd(&g_deg_in[d.x], 1); atomicAdd(&g_deg_in[d.y], 1);
        atomicAdd(&g_deg_in[d.z], 1); atomicAdd(&g_deg_in[d.w], 1);
    }
}

// ---------------- projection: h = (feat * deg_out^-1/2) @ W  -> fp16 ----------------
#define PROJ_ROWS 256
#define FPAD 65
__global__ void __launch_bounds__(256, 2)
k_proj(const float* __restrict__ feat, const float* __restrict__ weight) {
    extern __shared__ float smem[];
    float* Wsh = smem;                 // 4096 floats
    float* fsh = smem + 4096;          // 256*65 floats

    int tid = threadIdx.x;
    int B0  = blockIdx.x * PROJ_ROWS;

    #pragma unroll
    for (int i = 0; i < 4; i++)
        ((float4*)Wsh)[tid + i * 256] = ((const float4*)weight)[tid + i * 256];

    #pragma unroll
    for (int it = 0; it < 16; it++) {
        int idx = tid + it * 256;
        int row = idx >> 4;
        int c4  = idx & 15;
        int gr  = B0 + row;
        float4 v = make_float4(0.f, 0.f, 0.f, 0.f);
        if (gr < N_NODES) {
            float s = rsqrtf((float)max(g_deg_out[gr], 1));
            v = ((const float4*)feat)[gr * 16 + c4];
            v.x *= s; v.y *= s; v.z *= s; v.w *= s;
        }
        float* p = &fsh[row * FPAD + c4 * 4];
        p[0] = v.x; p[1] = v.y; p[2] = v.z; p[3] = v.w;
    }
    __syncthreads();

    int cg = tid & 3;
    int rg = tid >> 2;
    const u64* W2 = (const u64*)Wsh;
    const float* fr = &fsh[(rg * 4) * FPAD];

    u64 acc[4][8];
    #pragma unroll
    for (int r = 0; r < 4; r++)
        #pragma unroll
        for (int j = 0; j < 8; j++) acc[r][j] = 0ull;

    #pragma unroll 4
    for (int k = 0; k < D; k++) {
        u64 w[8];
        #pragma unroll
        for (int j = 0; j < 8; j++) w[j] = W2[k * 32 + cg * 8 + j];
        #pragma unroll
        for (int r = 0; r < 4; r++) {
            u64 ff = pack2(fr[r * FPAD + k]);
            #pragma unroll
            for (int j = 0; j < 8; j++) acc[r][j] = ffma2(ff, w[j], acc[r][j]);
        }
    }

    // store: 4 rows x 16 cols as fp16 -> one uint4 (8 half2) per row
    #pragma unroll
    for (int r = 0; r < 4; r++) {
        int gr = B0 + rg * 4 + r;
        if (gr < N_NODES) {
            uint4 o;
            o.x = cvt_h2(acc[r][0]); o.y = cvt_h2(acc[r][1]);
            o.z = cvt_h2(acc[r][2]); o.w = cvt_h2(acc[r][3]);
            ((uint4*)g_h)[gr * 8 + cg * 2 + 0] = o;
            o.x = cvt_h2(acc[r][4]); o.y = cvt_h2(acc[r][5]);
            o.z = cvt_h2(acc[r][6]); o.w = cvt_h2(acc[r][7]);
            ((uint4*)g_h)[gr * 8 + cg * 2 + 1] = o;
        }
    }
}

// ---------------- single-pass decoupled-lookback scan of deg_in ----------------
__device__ __forceinline__ int warp_incl_scan(int v, int lane) {
    #pragma unroll
    for (int off = 1; off < 32; off <<= 1) {
        int t = __shfl_up_sync(0xFFFFFFFFu, v, off);
        if (lane >= off) v += t;
    }
    return v;
}

__global__ void __launch_bounds__(SCAN_TPB, 1) k_scan() {
    __shared__ int sh_warp[SCAN_TPB / 32];
    __shared__ int sh_prefix;
    int tile = blockIdx.x;
    int tid  = threadIdx.x, lane = tid & 31, w = tid >> 5;
    int base = tile * SCAN_TILE + tid * SCAN_ITEMS;

    int v[SCAN_ITEMS];
    #pragma unroll
    for (int q = 0; q < 4; q++) {
        int idx = base + q * 4;
        int4 t = make_int4(0, 0, 0, 0);
        if (idx + 3 < N_NODES) {
            t = *(const int4*)&g_deg_in[idx];
        } else {
            if (idx + 0 < N_NODES) t.x = g_deg_in[idx + 0];
            if (idx + 1 < N_NODES) t.y = g_deg_in[idx + 1];
            if (idx + 2 < N_NODES) t.z = g_deg_in[idx + 2];
            if (idx + 3 < N_NODES) t.w = g_deg_in[idx + 3];
        }
        v[q * 4 + 0] = t.x; v[q * 4 + 1] = t.y;
        v[q * 4 + 2] = t.z; v[q * 4 + 3] = t.w;
    }
    #pragma unroll
    for (int i = 1; i < SCAN_ITEMS; i++) v[i] += v[i - 1];
    int tsum = v[SCAN_ITEMS - 1];

    int incl = warp_incl_scan(tsum, lane);
    if (lane == 31) sh_warp[w] = incl;
    __syncthreads();
    if (w == 0 && lane < SCAN_TPB / 32) {
        int x = sh_warp[lane];
        #pragma unroll
        for (int off = 1; off < SCAN_TPB / 32; off <<= 1) {
            int t = __shfl_up_sync(0xFFu, x, off);
            if (lane >= off) x += t;
        }
        sh_warp[lane] = x;
    }
    __syncthreads();
    int thread_excl = incl - tsum + (w > 0 ? sh_warp[w - 1] : 0);
    int block_sum   = sh_warp[SCAN_TPB / 32 - 1];

    if (tid == 0) {
        u64 st = (tile == 0) ? ((2ull << 32) | (unsigned)block_sum)
                             : ((1ull << 32) | (unsigned)block_sum);
        atomicExch(&g_tile_state[tile], st);
        if (tile == 0) sh_prefix = 0;
    }
    if (tile > 0 && w == 0) {
        int idx = tile - 1 - lane;
        int pfx = 0;
        for (;;) {
            u64 st = (idx >= 0) ? atomicAdd(&g_tile_state[idx], 0ull) : (2ull << 32);
            unsigned f = (unsigned)(st >> 32);
            unsigned bal2 = __ballot_sync(0xFFFFFFFFu, f == 2);
            unsigned bal1 = __ballot_sync(0xFFFFFFFFu, f >= 1);
            int l2 = __ffs(bal2) - 1;
            unsigned below = (1u << l2) - 1u;
            if ((bal1 & below) == below) {
                int val = (lane <= l2) ? (int)(unsigned)(st & 0xFFFFFFFFu) : 0;
                #pragma unroll
                for (int o = 16; o; o >>= 1) val += __shfl_xor_sync(0xFFFFFFFFu, val, o);
                pfx = val;
                break;
            }
        }
        if (lane == 0) {
            sh_prefix = pfx;
            atomicExch(&g_tile_state[tile], (2ull << 32) | (unsigned)(pfx + block_sum));
        }
    }
    __syncthreads();
    int pfx = sh_prefix;

    #pragma unroll
    for (int i = 0; i < SCAN_ITEMS; i++) {
        int idx = base + i;
        if (idx < N_NODES) {
            int e = pfx + thread_excl + (i ? v[i - 1] : 0);
            g_row_ptr[idx] = e;
            g_cursor[idx]  = e;
        }
    }
}

// ---------------- bucket-sort edges by dst ----------------
__global__ void k_bucket(const int* __restrict__ src, const int* __restrict__ dst) {
    int i = blockIdx.x * blockDim.x + threadIdx.x;
    if (i < N_EDGES / 4) {
        int4 s = ((const int4*)src)[i];
        int4 d = ((const int4*)dst)[i];
        g_esrc[atomicAdd(&g_cursor[d.x], 1)] = s.x;
        g_esrc[atomicAdd(&g_cursor[d.y], 1)] = s.y;
        g_esrc[atomicAdd(&g_cursor[d.z], 1)] = s.z;
        g_esrc[atomicAdd(&g_cursor[d.w], 1)] = s.w;
    }
}

// ---------------- gather (fp16 rows, fp32 accum) + epilogue ----------------
__global__ void k_gather(const float* __restrict__ bias, float* __restrict__ out) {
    int node = (blockIdx.x * blockDim.x + threadIdx.x) >> 5;
    int lane = threadIdx.x & 31;
    if (node >= N_NODES) return;
    int beg = g_row_ptr[node];
    int deg = g_deg_in[node];
    int end = beg + deg;
    const __half2* __restrict__ H2 = (const __half2*)g_h;

    float2 a0 = {0.f, 0.f}, a1 = {0.f, 0.f}, a2 = {0.f, 0.f}, a3 = {0.f, 0.f};
    int e = beg;
    for (; e + 4 <= end; e += 4) {
        int s0 = __ldg(&g_esrc[e + 0]);
        int s1 = __ldg(&g_esrc[e + 1]);
        int s2 = __ldg(&g_esrc[e + 2]);
        int s3 = __ldg(&g_esrc[e + 3]);
        float2 v0 = __half22float2(H2[s0 * 32 + lane]);
        float2 v1 = __half22float2(H2[s1 * 32 + lane]);
        float2 v2 = __half22float2(H2[s2 * 32 + lane]);
        float2 v3 = __half22float2(H2[s3 * 32 + lane]);
        a0.x += v0.x; a0.y += v0.y;
        a1.x += v1.x; a1.y += v1.y;
        a2.x += v2.x; a2.y += v2.y;
        a3.x += v3.x; a3.y += v3.y;
    }
    for (; e < end; e++) {
        int s = __ldg(&g_esrc[e]);
        float2 v = __half22float2(H2[s * 32 + lane]);
        a0.x += v.x; a0.y += v.y;
    }
    float sx = (a0.x + a1.x) + (a2.x + a3.x);
    float sy = (a0.y + a1.y) + (a2.y + a3.y);
    float sc = rsqrtf((float)max(deg, 1));
    float2 b = ((const float2*)bias)[lane];
    ((float2*)out)[node * 32 + lane] = make_float2(sx * sc + b.x, sy * sc + b.y);
}

// ---------------- stream/event resources (host-side, created once) ----------------
struct GcnRes {
    cudaStream_t s2 = nullptr;
    cudaEvent_t  ev_fork = nullptr, ev_join = nullptr;
    GcnRes() {
        cudaStreamCreateWithFlags(&s2, cudaStreamNonBlocking);
        cudaEventCreateWithFlags(&ev_fork, cudaEventDisableTiming);
        cudaEventCreateWithFlags(&ev_join, cudaEventDisableTiming);
    }
};
static GcnRes g_res;

extern "C" void kernel_launch(void* const* d_in, const int* in_sizes, int n_in,
                              void* d_out, int out_size) {
    const float* features = (const float*)d_in[0];
    const float* weight   = (const float*)d_in[1];
    const float* bias     = (const float*)d_in[2];
    const int*   src      = (const int*)d_in[3];
    const int*   dst      = (const int*)d_in[4];
    float* out = (float*)d_out;

    if (!g_res.s2) {
        cudaStreamCreateWithFlags(&g_res.s2, cudaStreamNonBlocking);
        cudaEventCreateWithFlags(&g_res.ev_fork, cudaEventDisableTiming);
        cudaEventCreateWithFlags(&g_res.ev_join, cudaEventDisableTiming);
    }

    static void* p_deg_out = nullptr;
    static void* p_deg_in  = nullptr;
    static void* p_state   = nullptr;
    static bool  attr_set  = false;
    if (!p_deg_out) {
        cudaGetSymbolAddress(&p_deg_out, g_deg_out);
        cudaGetSymbolAddress(&p_deg_in,  g_deg_in);
        cudaGetSymbolAddress(&p_state,   g_tile_state);
    }
    int proj_smem = (4096 + PROJ_ROWS * FPAD) * sizeof(float);
    if (!attr_set) {
        cudaFuncSetAttribute(k_proj, cudaFuncAttributeMaxDynamicSharedMemorySize, proj_smem);
        attr_set = true;
    }

    cudaStream_t ms = 0;
    cudaStream_t s2 = g_res.s2;

    cudaEventRecord(g_res.ev_fork, ms);
    cudaStreamWaitEvent(s2, g_res.ev_fork, 0);

    // ---- branch B: deg_in -> scan -> bucket ----
    cudaMemsetAsync(p_deg_in, 0, N_NODES * sizeof(int), s2);
    cudaMemsetAsync(p_state,  0, N_TILES * sizeof(u64), s2);
    k_deg_in <<<(N_EDGES / 4 + 255) / 256, 256, 0, s2>>>(dst);
    k_scan   <<<N_TILES, SCAN_TPB, 0, s2>>>();
    k_bucket <<<(N_EDGES / 4 + 255) / 256, 256, 0, s2>>>(src, dst);
    cudaEventRecord(g_res.ev_join, s2);

    // ---- branch A: deg_out -> proj ----
    cudaMemsetAsync(p_deg_out, 0, N_NODES * sizeof(int), ms);
    k_deg_out<<<(N_EDGES / 4 + 255) / 256, 256, 0, ms>>>(src);
    k_proj   <<<(N_NODES + PROJ_ROWS - 1) / PROJ_ROWS, 256, proj_smem, ms>>>(features, weight);

    // join + gather
    cudaStreamWaitEvent(ms, g_res.ev_join, 0);
    k_gather <<<(N_NODES * 32 + 255) / 256, 256, 0, ms>>>(bias, out);
}

// round 6
// speedup vs baseline: 1.4680x; 1.1265x over previous
#include <cuda_runtime.h>
#include <cuda_fp16.h>
#include <cuda_bf16.h>
#include <cstdint>

#define N_NODES 100000
#define N_EDGES 1250000
#define D 64

#define SCAN_TPB 256
#define SCAN_ITEMS 16
#define SCAN_TILE (SCAN_TPB * SCAN_ITEMS)                       // 4096
#define N_TILES ((N_NODES + SCAN_TILE - 1) / SCAN_TILE)          // 25

typedef unsigned long long u64;

// ---- scratch (no allocations allowed) ----
__device__ int    g_deg_out[N_NODES];
__device__ int    g_deg_in[N_NODES];
__device__ int    g_row_ptr[N_NODES];
__device__ int    g_cursor[N_NODES];
__device__ int    g_esrc[N_EDGES];
__device__ u64    g_tile_state[N_TILES];      // flag (hi 32) | value (lo 32)
__device__ __half g_h[N_NODES * D];           // projected rows (fp16)

// ---------------- degree histograms ----------------
__global__ void k_deg_out(const int* __restrict__ src) {
    int i = blockIdx.x * blockDim.x + threadIdx.x;
    if (i < N_EDGES / 4) {
        int4 s = ((const int4*)src)[i];
        atomicAdd(&g_deg_out[s.x], 1); atomicAdd(&g_deg_out[s.y], 1);
        atomicAdd(&g_deg_out[s.z], 1); atomicAdd(&g_deg_out[s.w], 1);
    }
}
__global__ void k_deg_in(const int* __restrict__ dst) {
    int i = blockIdx.x * blockDim.x + threadIdx.x;
    if (i < N_EDGES / 4) {
        int4 d = ((const int4*)dst)[i];
        atomicAdd(&g_deg_in[d.x], 1); atomicAdd(&g_deg_in[d.y], 1);
        atomicAdd(&g_deg_in[d.z], 1); atomicAdd(&g_deg_in[d.w], 1);
    }
}

// ====== projection via mma.sync (HMMA), 3xBF16 split ======
// h = (feat * deg_out^-1/2) @ W  ->  fp16 g_h
// block: 256 threads = 8 warps; warp w covers rows [B0 + 16w, B0 + 16w + 16).
#define PROJ_M 128
#define PROJ_BLOCKS ((N_NODES + PROJ_M - 1) / PROJ_M)   // 782
#define WT_PITCH 66

__device__ __forceinline__ void mma_bf16(float* d, const uint32_t* a, uint32_t b0, uint32_t b1) {
    asm volatile(
        "mma.sync.aligned.m16n8k16.row.col.f32.bf16.bf16.f32 "
        "{%0,%1,%2,%3}, {%4,%5,%6,%7}, {%8,%9}, {%0,%1,%2,%3};"
        : "+f"(d[0]), "+f"(d[1]), "+f"(d[2]), "+f"(d[3])
        : "r"(a[0]), "r"(a[1]), "r"(a[2]), "r"(a[3]), "r"(b0), "r"(b1));
}
__device__ __forceinline__ uint32_t bf16x2_hi(float x, float y) {
    __nv_bfloat162 h = __floats2bfloat162_rn(x, y);
    return *(uint32_t*)&h;
}

__global__ void __launch_bounds__(256)
k_proj(const float* __restrict__ feat, const float* __restrict__ weight) {
    __shared__ __nv_bfloat16 Wt[2][64 * WT_PITCH];   // [hi/lo][n * 66 + k]

    int tid  = threadIdx.x;
    int wid  = tid >> 5, lane = tid & 31;
    int B0   = blockIdx.x * PROJ_M;

    // stage W^T hi/lo (coalesced reads of W: n fast)
    for (int i = tid; i < 4096; i += 256) {
        int n = i & 63, k = i >> 6;
        float w = weight[k * 64 + n];
        __nv_bfloat16 hw = __float2bfloat16_rn(w);
        __nv_bfloat16 lw = __float2bfloat16_rn(w - __bfloat162float(hw));
        Wt[0][n * WT_PITCH + k] = hw;
        Wt[1][n * WT_PITCH + k] = lw;
    }
    __syncthreads();

    int g   = lane >> 2;        // 0..7
    int tig = lane & 3;         // 0..3
    int r0  = B0 + wid * 16 + g;
    int r1  = r0 + 8;
    bool v0 = r0 < N_NODES, v1 = r1 < N_NODES;
    float s0 = v0 ? rsqrtf((float)max(g_deg_out[r0], 1)) : 0.f;
    float s1 = v1 ? rsqrtf((float)max(g_deg_out[r1], 1)) : 0.f;

    float acc[8][4];
    #pragma unroll
    for (int n = 0; n < 8; n++)
        #pragma unroll
        for (int q = 0; q < 4; q++) acc[n][q] = 0.f;

    const float2 z2 = make_float2(0.f, 0.f);
    #pragma unroll
    for (int ks = 0; ks < 4; ks++) {
        int kb = ks * 16;
        float2 x0 = v0 ? *(const float2*)&feat[r0 * 64 + kb + tig * 2]     : z2;
        float2 x1 = v1 ? *(const float2*)&feat[r1 * 64 + kb + tig * 2]     : z2;
        float2 x2 = v0 ? *(const float2*)&feat[r0 * 64 + kb + tig * 2 + 8] : z2;
        float2 x3 = v1 ? *(const float2*)&feat[r1 * 64 + kb + tig * 2 + 8] : z2;
        x0.x *= s0; x0.y *= s0;  x1.x *= s1; x1.y *= s1;
        x2.x *= s0; x2.y *= s0;  x3.x *= s1; x3.y *= s1;

        uint32_t aHi[4], aLo[4];
        {
            float2 xs[4] = {x0, x1, x2, x3};
            #pragma unroll
            for (int j = 0; j < 4; j++) {
                __nv_bfloat162 h = __floats2bfloat162_rn(xs[j].x, xs[j].y);
                float2 hf = __bfloat1622float2(h);
                __nv_bfloat162 l = __floats2bfloat162_rn(xs[j].x - hf.x, xs[j].y - hf.y);
                aHi[j] = *(uint32_t*)&h;
                aLo[j] = *(uint32_t*)&l;
            }
        }

        #pragma unroll
        for (int nt = 0; nt < 8; nt++) {
            int c  = nt * 8 + g;
            int rr = kb + tig * 2;
            uint32_t bHi0 = *(const uint32_t*)&Wt[0][c * WT_PITCH + rr];
            uint32_t bHi1 = *(const uint32_t*)&Wt[0][c * WT_PITCH + rr + 8];
            uint32_t bLo0 = *(const uint32_t*)&Wt[1][c * WT_PITCH + rr];
            uint32_t bLo1 = *(const uint32_t*)&Wt[1][c * WT_PITCH + rr + 8];
            mma_bf16(acc[nt], aHi, bHi0, bHi1);
            mma_bf16(acc[nt], aHi, bLo0, bLo1);
            mma_bf16(acc[nt], aLo, bHi0, bHi1);
        }
    }

    // epilogue: fp32 -> fp16 pairs
    #pragma unroll
    for (int nt = 0; nt < 8; nt++) {
        int col = nt * 8 + tig * 2;
        if (v0) {
            __half2 p = __floats2half2_rn(acc[nt][0], acc[nt][1]);
            *(uint32_t*)&g_h[r0 * 64 + col] = *(uint32_t*)&p;
        }
        if (v1) {
            __half2 p = __floats2half2_rn(acc[nt][2], acc[nt][3]);
            *(uint32_t*)&g_h[r1 * 64 + col] = *(uint32_t*)&p;
        }
    }
}

// ---------------- single-pass decoupled-lookback scan of deg_in ----------------
__device__ __forceinline__ int warp_incl_scan(int v, int lane) {
    #pragma unroll
    for (int off = 1; off < 32; off <<= 1) {
        int t = __shfl_up_sync(0xFFFFFFFFu, v, off);
        if (lane >= off) v += t;
    }
    return v;
}

__global__ void __launch_bounds__(SCAN_TPB, 1) k_scan() {
    __shared__ int sh_warp[SCAN_TPB / 32];
    __shared__ int sh_prefix;
    int tile = blockIdx.x;
    int tid  = threadIdx.x, lane = tid & 31, w = tid >> 5;
    int base = tile * SCAN_TILE + tid * SCAN_ITEMS;

    int v[SCAN_ITEMS];
    #pragma unroll
    for (int q = 0; q < 4; q++) {
        int idx = base + q * 4;
        int4 t = make_int4(0, 0, 0, 0);
        if (idx + 3 < N_NODES) {
            t = *(const int4*)&g_deg_in[idx];
        } else {
            if (idx + 0 < N_NODES) t.x = g_deg_in[idx + 0];
            if (idx + 1 < N_NODES) t.y = g_deg_in[idx + 1];
            if (idx + 2 < N_NODES) t.z = g_deg_in[idx + 2];
            if (idx + 3 < N_NODES) t.w = g_deg_in[idx + 3];
        }
        v[q * 4 + 0] = t.x; v[q * 4 + 1] = t.y;
        v[q * 4 + 2] = t.z; v[q * 4 + 3] = t.w;
    }
    #pragma unroll
    for (int i = 1; i < SCAN_ITEMS; i++) v[i] += v[i - 1];
    int tsum = v[SCAN_ITEMS - 1];

    int incl = warp_incl_scan(tsum, lane);
    if (lane == 31) sh_warp[w] = incl;
    __syncthreads();
    if (w == 0 && lane < SCAN_TPB / 32) {
        int x = sh_warp[lane];
        #pragma unroll
        for (int off = 1; off < SCAN_TPB / 32; off <<= 1) {
            int t = __shfl_up_sync(0xFFu, x, off);
            if (lane >= off) x += t;
        }
        sh_warp[lane] = x;
    }
    __syncthreads();
    int thread_excl = incl - tsum + (w > 0 ? sh_warp[w - 1] : 0);
    int block_sum   = sh_warp[SCAN_TPB / 32 - 1];

    if (tid == 0) {
        u64 st = (tile == 0) ? ((2ull << 32) | (unsigned)block_sum)
                             : ((1ull << 32) | (unsigned)block_sum);
        atomicExch(&g_tile_state[tile], st);
        if (tile == 0) sh_prefix = 0;
    }
    if (tile > 0 && w == 0) {
        int idx = tile - 1 - lane;
        int pfx = 0;
        for (;;) {
            u64 st = (idx >= 0) ? atomicAdd(&g_tile_state[idx], 0ull) : (2ull << 32);
            unsigned f = (unsigned)(st >> 32);
            unsigned bal2 = __ballot_sync(0xFFFFFFFFu, f == 2);
            unsigned bal1 = __ballot_sync(0xFFFFFFFFu, f >= 1);
            int l2 = __ffs(bal2) - 1;
            unsigned below = (1u << l2) - 1u;
            if ((bal1 & below) == below) {
                int val = (lane <= l2) ? (int)(unsigned)(st & 0xFFFFFFFFu) : 0;
                #pragma unroll
                for (int o = 16; o; o >>= 1) val += __shfl_xor_sync(0xFFFFFFFFu, val, o);
                pfx = val;
                break;
            }
        }
        if (lane == 0) {
            sh_prefix = pfx;
            atomicExch(&g_tile_state[tile], (2ull << 32) | (unsigned)(pfx + block_sum));
        }
    }
    __syncthreads();
    int pfx = sh_prefix;

    #pragma unroll
    for (int i = 0; i < SCAN_ITEMS; i++) {
        int idx = base + i;
        if (idx < N_NODES) {
            int e = pfx + thread_excl + (i ? v[i - 1] : 0);
            g_row_ptr[idx] = e;
            g_cursor[idx]  = e;
        }
    }
}

// ---------------- bucket-sort edges by dst ----------------
__global__ void k_bucket(const int* __restrict__ src, const int* __restrict__ dst) {
    int i = blockIdx.x * blockDim.x + threadIdx.x;
    if (i < N_EDGES / 4) {
        int4 s = ((const int4*)src)[i];
        int4 d = ((const int4*)dst)[i];
        g_esrc[atomicAdd(&g_cursor[d.x], 1)] = s.x;
        g_esrc[atomicAdd(&g_cursor[d.y], 1)] = s.y;
        g_esrc[atomicAdd(&g_cursor[d.z], 1)] = s.z;
        g_esrc[atomicAdd(&g_cursor[d.w], 1)] = s.w;
    }
}

// ---------------- gather (fp16 rows, fp32 accum) + epilogue ----------------
__global__ void k_gather(const float* __restrict__ bias, float* __restrict__ out) {
    int node = (blockIdx.x * blockDim.x + threadIdx.x) >> 5;
    int lane = threadIdx.x & 31;
    if (node >= N_NODES) return;
    int beg = g_row_ptr[node];
    int deg = g_deg_in[node];
    int end = beg + deg;
    const __half2* __restrict__ H2 = (const __half2*)g_h;

    float2 a0 = {0.f, 0.f}, a1 = {0.f, 0.f}, a2 = {0.f, 0.f}, a3 = {0.f, 0.f};
    int e = beg;
    for (; e + 4 <= end; e += 4) {
        int s0 = __ldg(&g_esrc[e + 0]);
        int s1 = __ldg(&g_esrc[e + 1]);
        int s2 = __ldg(&g_esrc[e + 2]);
        int s3 = __ldg(&g_esrc[e + 3]);
        float2 v0 = __half22float2(H2[s0 * 32 + lane]);
        float2 v1 = __half22float2(H2[s1 * 32 + lane]);
        float2 v2 = __half22float2(H2[s2 * 32 + lane]);
        float2 v3 = __half22float2(H2[s3 * 32 + lane]);
        a0.x += v0.x; a0.y += v0.y;
        a1.x += v1.x; a1.y += v1.y;
        a2.x += v2.x; a2.y += v2.y;
        a3.x += v3.x; a3.y += v3.y;
    }
    for (; e < end; e++) {
        int s = __ldg(&g_esrc[e]);
        float2 v = __half22float2(H2[s * 32 + lane]);
        a0.x += v.x; a0.y += v.y;
    }
    float sx = (a0.x + a1.x) + (a2.x + a3.x);
    float sy = (a0.y + a1.y) + (a2.y + a3.y);
    float sc = rsqrtf((float)max(deg, 1));
    float2 b = ((const float2*)bias)[lane];
    ((float2*)out)[node * 32 + lane] = make_float2(sx * sc + b.x, sy * sc + b.y);
}

// ---------------- stream/event resources ----------------
struct GcnRes {
    cudaStream_t s2 = nullptr;
    cudaEvent_t  ev_fork = nullptr, ev_join = nullptr;
    GcnRes() {
        cudaStreamCreateWithFlags(&s2, cudaStreamNonBlocking);
        cudaEventCreateWithFlags(&ev_fork, cudaEventDisableTiming);
        cudaEventCreateWithFlags(&ev_join, cudaEventDisableTiming);
    }
};
static GcnRes g_res;

extern "C" void kernel_launch(void* const* d_in, const int* in_sizes, int n_in,
                              void* d_out, int out_size) {
    const float* features = (const float*)d_in[0];
    const float* weight   = (const float*)d_in[1];
    const float* bias     = (const float*)d_in[2];
    const int*   src      = (const int*)d_in[3];
    const int*   dst      = (const int*)d_in[4];
    float* out = (float*)d_out;

    if (!g_res.s2) {
        cudaStreamCreateWithFlags(&g_res.s2, cudaStreamNonBlocking);
        cudaEventCreateWithFlags(&g_res.ev_fork, cudaEventDisableTiming);
        cudaEventCreateWithFlags(&g_res.ev_join, cudaEventDisableTiming);
    }

    static void* p_deg_out = nullptr;
    static void* p_deg_in  = nullptr;
    static void* p_state   = nullptr;
    if (!p_deg_out) {
        cudaGetSymbolAddress(&p_deg_out, g_deg_out);
        cudaGetSymbolAddress(&p_deg_in,  g_deg_in);
        cudaGetSymbolAddress(&p_state,   g_tile_state);
    }

    cudaStream_t ms = 0;
    cudaStream_t s2 = g_res.s2;

    cudaEventRecord(g_res.ev_fork, ms);
    cudaStreamWaitEvent(s2, g_res.ev_fork, 0);

    // ---- branch B: deg_in -> scan -> bucket ----
    cudaMemsetAsync(p_deg_in, 0, N_NODES * sizeof(int), s2);
    cudaMemsetAsync(p_state,  0, N_TILES * sizeof(u64), s2);
    k_deg_in <<<(N_EDGES / 4 + 255) / 256, 256, 0, s2>>>(dst);
    k_scan   <<<N_TILES, SCAN_TPB, 0, s2>>>();
    k_bucket <<<(N_EDGES / 4 + 255) / 256, 256, 0, s2>>>(src, dst);
    cudaEventRecord(g_res.ev_join, s2);

    // ---- branch A: deg_out -> proj (HMMA) ----
    cudaMemsetAsync(p_deg_out, 0, N_NODES * sizeof(int), ms);
    k_deg_out<<<(N_EDGES / 4 + 255) / 256, 256, 0, ms>>>(src);
    k_proj   <<<PROJ_BLOCKS, 256, 0, ms>>>(features, weight);

    // join + gather
    cudaStreamWaitEvent(ms, g_res.ev_join, 0);
    k_gather <<<(N_NODES * 32 + 255) / 256, 256, 0, ms>>>(bias, out);
}